// round 11
// baseline (speedup 1.0000x reference)
#include <cuda_runtime.h>
#include <cstdint>
#include <cstddef>

// Problem constants
#define NEMB   1024
#define EDIM   256
#define BATCH  8
#define HWL    4096
#define NROWS  32768
#define MT     128
#define NBLK   256
#define NCHK   16            // 16 chunks of 64 codes
#define CAP    4096

// smem byte offsets (all 16B aligned)
#define SM_ZQ    0           // 128*65 ints   = 33280
#define SM_EB    33280       // 2*64*65 ints  = 33280
#define EBB      16640
#define SM_E2    66560       // 2*64 floats   = 512
#define SM_Z2    67072       // 128 floats
#define SM_CR    67584       // 128 floats
#define SM_EP    68096       // 128 floats
#define SM_V     68608       // 2*128 floats
#define SM_BEST  69632       // 128 u64
#define SM_CAND  70656       // 4096 u32
#define SM_CNT   87040
#define SM_TOTAL 87072

// Scratch
__device__ float  g_zf[NROWS*EDIM];   // z transposed (N, D) fp32
__device__ int    g_zq[NROWS*64];     // z int8 packed (4 dims/int)
__device__ int    g_eq[NEMB*64];      // codebook int8 packed
__device__ float  g_e2[NEMB];
__device__ float  g_z2[NROWS];
__device__ float  g_cr[NROWS];        // 2*s_r/(127*130048)
__device__ float  g_eps[NROWS];       // rigorous screening window
__device__ int    g_idx[NROWS];
__device__ double g_partial[NBLK];

// ---------------- helpers ----------------
__device__ __forceinline__ uint32_t smem_u32(const void* p) {
    uint32_t a;
    asm("{ .reg .u64 t; cvta.to.shared.u64 t, %1; cvt.u32.u64 %0, t; }" : "=r"(a) : "l"(p));
    return a;
}
__device__ __forceinline__ void cpa4(uint32_t dst, const void* src) {
    asm volatile("cp.async.ca.shared.global [%0], [%1], 4;" :: "r"(dst), "l"(src));
}
#define CP_COMMIT() asm volatile("cp.async.commit_group;" ::: "memory")
#define CP_WAIT1()  asm volatile("cp.async.wait_group 1;" ::: "memory")
#define CP_WAIT0()  asm volatile("cp.async.wait_group 0;" ::: "memory")

// exact fp32 distance — IDENTICAL pipeline to the passing R2/R7 kernels
__device__ __forceinline__ float exact_dist(int nrow, int k, float z2r,
                                            const float* __restrict__ cb) {
    const float* zr = g_zf + (size_t)nrow*EDIM;
    const float* er = cb   + (size_t)k*EDIM;
    float s0 = 0.f, s1 = 0.f;
    #pragma unroll 8
    for (int d = 0; d < EDIM; d += 2) {
        s0 += zr[d]   * er[d];
        s1 += zr[d+1] * er[d+1];
    }
    return (z2r + g_e2[k]) - 2.f*(s0 + s1);
}

// ---------------------------------------------------------------------------
// Kernel A: transpose z (B, D, HWL) -> zf (B*HWL, D)
// ---------------------------------------------------------------------------
__global__ void vq_transpose(const float* __restrict__ z) {
    __shared__ float tile[32][33];
    int b = blockIdx.z, d0 = blockIdx.y << 5, s0 = blockIdx.x << 5;
    int tx = threadIdx.x, ty = threadIdx.y;
    const float* src = z + ((size_t)b*EDIM + d0)*HWL + s0;
    #pragma unroll
    for (int i = 0; i < 32; i += 8)
        tile[ty+i][tx] = src[(size_t)(ty+i)*HWL + tx];
    __syncthreads();
    float* dst = g_zf + ((size_t)b*HWL + s0)*EDIM + d0;
    #pragma unroll
    for (int i = 0; i < 32; i += 8)
        dst[(size_t)(ty+i)*EDIM + tx] = tile[tx][ty+i];
}

// ---------------------------------------------------------------------------
// Kernel B: codebook row norms (double accumulate -> correctly rounded fp32)
// ---------------------------------------------------------------------------
__global__ void vq_e2(const float* __restrict__ cb) {
    int k = blockIdx.x * blockDim.x + threadIdx.x;
    if (k < NEMB) {
        const float* row = cb + (size_t)k*EDIM;
        double s = 0.0;
        for (int d = 0; d < EDIM; d++) { double v = row[d]; s += v*v; }
        g_e2[k] = (float)s;
    }
}

// ---------------------------------------------------------------------------
// Kernel B2: pack codebook to int8 (scale 127*1024; exact range fit)
// ---------------------------------------------------------------------------
__global__ __launch_bounds__(256)
void vq_packe(const float* __restrict__ cb) {
    int row = blockIdx.x*8 + (threadIdx.x >> 5);
    int lane = threadIdx.x & 31;
    const float* er = cb + (size_t)row*EDIM + lane*8;
    int out[2];
    #pragma unroll
    for (int half = 0; half < 2; half++) {
        float4 v = *(const float4*)(er + half*4);
        int q0 = max(-127, min(127, __float2int_rn(v.x*130048.f)));
        int q1 = max(-127, min(127, __float2int_rn(v.y*130048.f)));
        int q2 = max(-127, min(127, __float2int_rn(v.z*130048.f)));
        int q3 = max(-127, min(127, __float2int_rn(v.w*130048.f)));
        out[half] = (q0 & 255) | ((q1 & 255) << 8) | ((q2 & 255) << 16) | (q3 << 24);
    }
    *(int2*)(g_eq + row*64 + lane*2) = make_int2(out[0], out[1]);
}

// ---------------------------------------------------------------------------
// Kernel B3: pack z rows to int8 + per-row stats.
// 32 rows per block; ONLY threads t<64 (2 per row) do stats+pack — this was
// the R9 OOB bug (r ran to 127 against a 32-row tile and wrote past g_zq).
// z2 summation order bit-matches the passing R2 pipeline (half sums, then add).
// ---------------------------------------------------------------------------
__global__ __launch_bounds__(256)
void vq_packz() {
    __shared__ float zt[32*257];
    int t = threadIdx.x;
    int rows = blockIdx.x * 32;
    for (int i = t; i < 32*64; i += 256) {
        int r = i >> 6, c4 = (i & 63) << 2;
        float4 v = *(const float4*)(g_zf + (size_t)(rows + r)*EDIM + c4);
        float* d = zt + r*257 + c4;
        d[0] = v.x; d[1] = v.y; d[2] = v.z; d[3] = v.w;
    }
    __syncthreads();
    if (t < 64) {
        int r = t >> 1, h = t & 1;
        int row = rows + r;
        const float* p = zt + r*257 + h*128;
        float s = 0.f, amax = 0.f, asum = 0.f;
        #pragma unroll 8
        for (int d = 0; d < 128; d++) {
            float v = p[d];
            s += v*v;
            float av = fabsf(v);
            amax = fmaxf(amax, av);
            asum += av;
        }
        float so = __shfl_xor_sync(0xffffffffu, s, 1);
        amax = fmaxf(amax, __shfl_xor_sync(0xffffffffu, amax, 1));
        asum += __shfl_xor_sync(0xffffffffu, asum, 1);
        if (!h) {
            g_z2[row] = s + so;                     // R2 ordering
            g_cr[row] = amax * (2.f/16516096.f);
            g_eps[row] = 4.f*(amax*(0.18f/254.f) + asum*(1.f/260096.f)) + 2e-3f;
        }
        float scale = (amax > 0.f) ? (127.f/amax) : 0.f;
        #pragma unroll 4
        for (int w = 0; w < 32; w++) {
            const float* q = p + w*4;
            int q0 = __float2int_rn(q[0]*scale);
            int q1 = __float2int_rn(q[1]*scale);
            int q2 = __float2int_rn(q[2]*scale);
            int q3 = __float2int_rn(q[3]*scale);
            g_zq[row*64 + h*32 + w] =
                (q0 & 255) | ((q1 & 255) << 8) | ((q2 & 255) << 16) | (q3 << 24);
        }
    }
}

// ---------------------------------------------------------------------------
// chunk loader: 64 codes x 64 ints + 64 e2 floats via cp.async (4B, pitch 65)
// ---------------------------------------------------------------------------
__device__ __forceinline__ void loadE(uint32_t sb, int cc, int t) {
    int buf = cc & 1;
    const int* src = g_eq + cc*64*64;
    uint32_t dst = sb + SM_EB + buf*EBB;
    #pragma unroll
    for (int j = 0; j < 16; j++) {
        int i = t + j*256;
        int n = i >> 6, q = i & 63;
        cpa4(dst + (uint32_t)(n*65 + q)*4, src + n*64 + q);
    }
    if (t < 64) cpa4(sb + SM_E2 + buf*256 + t*4, g_e2 + cc*64 + t);
    CP_COMMIT();
}

// ---------------------------------------------------------------------------
// Kernel C: int8 dp4a GEMM + running-min screening + exact fp32 rescore
// 256 threads = 8 warps (4 row-warps x 2 col-warps); warp tile 32x32;
// lane = 4 row-groups x 8 code-groups; thread tile 8 rows x 4 codes.
// ---------------------------------------------------------------------------
__global__ __launch_bounds__(256, 2)
void vq_screen(const float* __restrict__ cb, float* __restrict__ out_idx, int write_idx) {
    extern __shared__ char smc[];
    uint32_t sb = smem_u32(smc);
    int*   zq   = (int*)(smc + SM_ZQ);
    float* z2s  = (float*)(smc + SM_Z2);
    float* crs  = (float*)(smc + SM_CR);
    float* epss = (float*)(smc + SM_EP);
    float* V    = (float*)(smc + SM_V);
    unsigned long long* best = (unsigned long long*)(smc + SM_BEST);
    unsigned* cand = (unsigned*)(smc + SM_CAND);
    int* scnt = (int*)(smc + SM_CNT);

    const int t = threadIdx.x, lane = t & 31, w = t >> 5;
    const int rw = w >> 1, cw = w & 1;
    const int rg = lane >> 3, cg = lane & 7;
    const int rowbase = rw*32 + rg*8;
    const int colbase = cw*32 + cg*4;          // within 64-code chunk
    const int n0 = blockIdx.x * MT;

    // init + per-row stats
    if (t < MT) {
        V[t] = 3.4e38f; V[MT + t] = 3.4e38f; best[t] = ~0ull;
        z2s[t]  = g_z2[n0 + t];
        crs[t]  = g_cr[n0 + t];
        epss[t] = g_eps[n0 + t];
    }
    if (t == 0) *scnt = 0;

    loadE(sb, 0, t);
    loadE(sb, 1, t);

    // z int8 tile -> smem (pitch 65)
    for (int i = t; i < MT*16; i += 256) {
        int r = i >> 4, q4 = (i & 15) << 2;
        int4 v = *(const int4*)(g_zq + (n0 + r)*64 + q4);
        int* d = zq + r*65 + q4;
        d[0] = v.x; d[1] = v.y; d[2] = v.z; d[3] = v.w;
    }

    for (int cc = 0; cc < NCHK; cc++) {
        int buf = cc & 1;
        if (cc + 1 < NCHK) CP_WAIT1(); else CP_WAIT0();
        __syncthreads();                       // covers init/zq on cc==0 too

        const int* Zs = zq + rowbase*65;
        const int* Es = (const int*)(smc + SM_EB + buf*EBB) + colbase*65;
        const float* e2c = (const float*)(smc + SM_E2 + buf*256);

        int acc[8][4];
        #pragma unroll
        for (int i = 0; i < 8; i++)
            #pragma unroll
            for (int j = 0; j < 4; j++) acc[i][j] = 0;

        #pragma unroll 4
        for (int d4 = 0; d4 < 64; d4++) {
            int b0 = Es[d4], b1 = Es[65 + d4], b2 = Es[130 + d4], b3 = Es[195 + d4];
            #pragma unroll
            for (int i = 0; i < 8; i++) {
                int a = Zs[i*65 + d4];
                acc[i][0] = __dp4a(a, b0, acc[i][0]);
                acc[i][1] = __dp4a(a, b1, acc[i][1]);
                acc[i][2] = __dp4a(a, b2, acc[i][2]);
                acc[i][3] = __dp4a(a, b3, acc[i][3]);
            }
        }

        // 1) per-row chunk min -> update running min V
        #pragma unroll
        for (int i = 0; i < 8; i++) {
            int row = rowbase + i;
            float z2r = z2s[row], cr = crs[row];
            float m = 3.4e38f;
            #pragma unroll
            for (int j = 0; j < 4; j++) {
                float dd = (z2r + e2c[colbase + j]) - (float)acc[i][j]*cr;
                m = fminf(m, dd);
            }
            m = fminf(m, __shfl_down_sync(0xffffffffu, m, 4, 8));
            m = fminf(m, __shfl_down_sync(0xffffffffu, m, 2, 8));
            m = fminf(m, __shfl_down_sync(0xffffffffu, m, 1, 8));
            if (cg == 0) {
                float* vp = V + cw*MT + row;
                *vp = fminf(*vp, m);
            }
        }
        __syncwarp();
        // 2) candidate scan vs running min (+eps_r): provable superset of argmin
        #pragma unroll
        for (int i = 0; i < 8; i++) {
            int row = rowbase + i;
            float z2r = z2s[row], cr = crs[row];
            float thr = fminf(V[row], V[MT + row]) + epss[row];
            #pragma unroll
            for (int j = 0; j < 4; j++) {
                float dd = (z2r + e2c[colbase + j]) - (float)acc[i][j]*cr;
                if (dd <= thr) {
                    int k = cc*64 + colbase + j;
                    int idx = atomicAdd(scnt, 1);
                    if (idx < CAP) {
                        cand[idx] = ((unsigned)row << 16) | (unsigned)k;
                    } else {
                        float de = exact_dist(n0 + row, k, z2r, cb);
                        unsigned long long key =
                            ((unsigned long long)__float_as_uint(de) << 32) | (unsigned)k;
                        atomicMin(best + row, key);
                    }
                }
            }
        }
        __syncthreads();                       // all reads of buf done before refill
        if (cc + 2 < NCHK) loadE(sb, cc + 2, t);
    }

    __syncthreads();
    // cooperative exact rescore (fp32 pipeline identical to passing kernels)
    int cnt = *scnt; if (cnt > CAP) cnt = CAP;
    for (int i = t; i < cnt; i += 256) {
        unsigned pk = cand[i];
        int row = (int)(pk >> 16), k = (int)(pk & 0xFFFFu);
        float de = exact_dist(n0 + row, k, z2s[row], cb);
        unsigned long long key = ((unsigned long long)__float_as_uint(de) << 32) | (unsigned)k;
        atomicMin(best + row, key);            // positive fp32 bit-monotonic; ties -> smaller k
    }
    __syncthreads();

    float* vmin = crs;                          // reuse
    if (t < MT) {
        unsigned long long kb = best[t];
        int k = (int)(kb & 0xFFFFFFFFull);
        g_idx[n0 + t] = k;
        if (write_idx) out_idx[n0 + t] = (float)k;
        vmin[t] = __uint_as_float((unsigned)(kb >> 32));
    }
    __syncthreads();
    if (t == 0) {
        double s = 0.0;
        for (int r = 0; r < MT; r++) s += (double)vmin[r];
        g_partial[blockIdx.x] = s;              // deterministic
    }
}

// ---------------------------------------------------------------------------
// Kernel D: gather codebook rows by index, write (B, D, HWL)
// ---------------------------------------------------------------------------
__global__ __launch_bounds__(256)
void vq_scatter(const float* __restrict__ cb, float* __restrict__ outq) {
    __shared__ float qt[32*257];
    int b = blockIdx.y, s0 = blockIdx.x << 5, t = threadIdx.x;
    for (int i = t; i < 32*64; i += 256) {
        int r = i >> 6, c4 = i & 63;
        int k = g_idx[b*HWL + s0 + r];
        float4 v = *(const float4*)(cb + (size_t)k*EDIM + (c4 << 2));
        float* dst = qt + r*257 + (c4 << 2);
        dst[0] = v.x; dst[1] = v.y; dst[2] = v.z; dst[3] = v.w;
    }
    __syncthreads();
    int s = t & 31, dh = t >> 5;
    #pragma unroll
    for (int d = dh; d < EDIM; d += 8)
        outq[((size_t)b*EDIM + d)*HWL + s0 + s] = qt[s*257 + d];
}

// ---------------------------------------------------------------------------
// Kernel E: loss = 1.25 * sum(min_dist) / (N*D)
// ---------------------------------------------------------------------------
__global__ void vq_finalize(float* out_loss) {
    double s = 0.0;
    for (int i = 0; i < NBLK; i++) s += g_partial[i];
    *out_loss = (float)(1.25 * s / (double)((size_t)NROWS*EDIM));
}

// ---------------------------------------------------------------------------
extern "C" void kernel_launch(void* const* d_in, const int* in_sizes, int n_in,
                              void* d_out, int out_size) {
    const float* z  = (const float*)d_in[0];
    const float* cb = (const float*)d_in[1];
    if (n_in >= 2 && in_sizes[0] == NEMB*EDIM && in_sizes[1] == NROWS*EDIM) {
        const float* tmp = z; z = cb; cb = tmp;
    }
    float* out = (float*)d_out;

    const int QN = NROWS*EDIM;
    bool has_quant = (out_size >= QN);
    bool full      = (out_size == QN + NROWS + 1);
    float* out_idx  = full ? out + QN         : nullptr;
    float* out_loss = full ? out + QN + NROWS : nullptr;

    cudaFuncSetAttribute(vq_screen, cudaFuncAttributeMaxDynamicSharedMemorySize, SM_TOTAL);

    vq_transpose<<<dim3(HWL/32, EDIM/32, BATCH), dim3(32, 8)>>>(z);
    vq_e2<<<(NEMB + 255)/256, 256>>>(cb);
    vq_packe<<<NEMB/8, 256>>>(cb);
    vq_packz<<<NROWS/32, 256>>>();
    vq_screen<<<NBLK, 256, SM_TOTAL>>>(cb, out_idx, full ? 1 : 0);
    if (has_quant)
        vq_scatter<<<dim3(HWL/32, BATCH), 256>>>(cb, out);
    if (full)
        vq_finalize<<<1, 1>>>(out_loss);
}